// round 6
// baseline (speedup 1.0000x reference)
#include <cuda_runtime.h>
#include <cuda_bf16.h>
#include <stdint.h>

// Shapes: B=2, S=4096, H=1024, M=B*S=8192
#define BDIM 2
#define SDIM 4096
#define HDIM 1024
#define MDIM 8192

// GEMM tile config
#define TM 128
#define TN 128
#define TKB 32                 // K elements (bf16) per smem stage
#define ROWB 80                // bytes per smem row (64B payload + 16B pad)
#define TILE_BYTES (128 * ROWB)        // 10240
#define SA_HI 0
#define SA_LO (TILE_BYTES)
#define SB_HI (2 * TILE_BYTES)
#define SB_LO (3 * TILE_BYTES)
#define STAGE_BYTES (4 * TILE_BYTES)   // 40960
#define DSMEM_BYTES (2 * STAGE_BYTES)  // 81920 -> 2 CTAs/SM

// ---------------- scratch (device globals) ----------------
__device__ __nv_bfloat16 g_xhi[(size_t)MDIM*HDIM],  g_xlo[(size_t)MDIM*HDIM];
__device__ __nv_bfloat16 g_wqhi[(size_t)HDIM*HDIM], g_wqlo[(size_t)HDIM*HDIM];
__device__ __nv_bfloat16 g_wkhi[(size_t)HDIM*HDIM], g_wklo[(size_t)HDIM*HDIM];
__device__ __nv_bfloat16 g_wvhi[(size_t)HDIM*HDIM], g_wvlo[(size_t)HDIM*HDIM];
__device__ __nv_bfloat16 g_wohi[(size_t)HDIM*HDIM], g_wolo[(size_t)HDIM*HDIM];
__device__ __nv_bfloat16 g_qhi[(size_t)MDIM*HDIM],  g_qlo[(size_t)MDIM*HDIM];
__device__ __nv_bfloat16 g_khi[(size_t)MDIM*HDIM],  g_klo[(size_t)MDIM*HDIM];
__device__ __nv_bfloat16 g_vthi[(size_t)HDIM*MDIM], g_vtlo[(size_t)HDIM*MDIM];
__device__ __nv_bfloat16 g_athi[(size_t)MDIM*HDIM], g_atlo[(size_t)MDIM*HDIM];
__device__ __nv_bfloat16 g_phi[(size_t)BDIM*SDIM*SDIM], g_plo[(size_t)BDIM*SDIM*SDIM];
__device__ float g_s[(size_t)BDIM*SDIM*SDIM];

// ---------------- PTX helpers ----------------
__device__ __forceinline__ void cp16(void* dst, const void* src) {
    uint32_t d = (uint32_t)__cvta_generic_to_shared(dst);
    asm volatile("cp.async.cg.shared.global [%0], [%1], 16;\n" :: "r"(d), "l"(src));
}
#define CP_COMMIT() asm volatile("cp.async.commit_group;\n" ::: "memory")
#define CP_WAIT(n)  asm volatile("cp.async.wait_group %0;\n" :: "n"(n) : "memory")

__device__ __forceinline__ void mma_bf16(float* d, const uint32_t* a, const uint32_t* b) {
    asm volatile(
        "mma.sync.aligned.m16n8k16.row.col.f32.bf16.bf16.f32 "
        "{%0,%1,%2,%3}, {%4,%5,%6,%7}, {%8,%9}, {%0,%1,%2,%3};\n"
        : "+f"(d[0]), "+f"(d[1]), "+f"(d[2]), "+f"(d[3])
        : "r"(a[0]), "r"(a[1]), "r"(a[2]), "r"(a[3]), "r"(b[0]), "r"(b[1]));
}

__device__ __forceinline__ void ldsm4(uint32_t* r, uint32_t addr) {
    asm volatile("ldmatrix.sync.aligned.m8n8.x4.shared.b16 {%0,%1,%2,%3}, [%4];"
                 : "=r"(r[0]), "=r"(r[1]), "=r"(r[2]), "=r"(r[3]) : "r"(addr));
}

// ---------------------------------------------------------------------------
// Stage loader: A tile (128 x 32) hi/lo, B tile (128 x 32) hi/lo -> smem.
// ---------------------------------------------------------------------------
__device__ __forceinline__ void stage_loads(
    char* base, int tid,
    const __nv_bfloat16* Ah, const __nv_bfloat16* Al, long long ldA, long long m0,
    const __nv_bfloat16* Bh, const __nv_bfloat16* Bl, long long ldB, long long n0,
    long long kof)
{
    #pragma unroll
    for (int i = 0; i < 2; i++) {
        int idx = tid + i * 256;
        int r = idx >> 2, ch = idx & 3;
        int so = r * ROWB + ch * 16;
        long long goA = (m0 + r) * ldA + kof + ch * 8;
        long long goB = (n0 + r) * ldB + kof + ch * 8;
        cp16(base + SA_HI + so, Ah + goA);
        cp16(base + SA_LO + so, Al + goA);
        cp16(base + SB_HI + so, Bh + goB);
        cp16(base + SB_LO + so, Bl + goB);
    }
}

// ---------------------------------------------------------------------------
// One split term over a stage: ldmatrix fragment loads + 2 k-steps of
// m16n8k16 over warp tile 64x32. One fragment set live at a time.
// a_off/b_off: per-lane ldmatrix offsets (incl. warp tile base).
// ---------------------------------------------------------------------------
__device__ __forceinline__ void compute_term(
    uint32_t at, uint32_t bt, uint32_t a_off, uint32_t b_off,
    float acc[4][4][4])
{
    #pragma unroll
    for (int ks = 0; ks < 2; ks++) {
        uint32_t af[4][4], bf[4][2];
        #pragma unroll
        for (int mt = 0; mt < 4; mt++)
            ldsm4(af[mt], at + a_off + mt * (16 * ROWB) + ks * 32);
        #pragma unroll
        for (int np = 0; np < 2; np++) {
            uint32_t q[4];
            ldsm4(q, bt + b_off + np * (16 * ROWB) + ks * 32);
            bf[2 * np][0] = q[0];     bf[2 * np][1] = q[1];
            bf[2 * np + 1][0] = q[2]; bf[2 * np + 1][1] = q[3];
        }
        #pragma unroll
        for (int mt = 0; mt < 4; mt++)
            #pragma unroll
            for (int nt = 0; nt < 4; nt++)
                mma_bf16(acc[mt][nt], af[mt], bf[nt]);
    }
}

// ---------------------------------------------------------------------------
// NT GEMM, bf16 hi/lo split operands (3 terms: hh + hl + lh), fp32 accum:
//   C[m,n] = alpha * sum_k (Ahi+Alo)[m,k]*(Bhi+Blo)[n,k] + bias
// Output: fp32 (Cf) or bf16 hi/lo pair (Chi/Clo).
// bias_mode: 0 none, 1 per-column (n), 2 per-row (m).
// ---------------------------------------------------------------------------
__global__ __launch_bounds__(256, 2)
void gemm_nt_bf3(const __nv_bfloat16* __restrict__ Ah, const __nv_bfloat16* __restrict__ Al, long long ldA,
                 const __nv_bfloat16* __restrict__ Bh, const __nv_bfloat16* __restrict__ Bl, long long ldB,
                 float* __restrict__ Cf, __nv_bfloat16* __restrict__ Chi, __nv_bfloat16* __restrict__ Clo,
                 long long ldC,
                 const float* __restrict__ bias, int bias_mode, float alpha, int K,
                 long long sA, long long sB, long long sC)
{
    extern __shared__ char smem[];

    const int tid  = threadIdx.x;
    const int lane = tid & 31;
    const int wid  = tid >> 5;
    const int warp_m = wid & 1;   // 2 x 64 rows
    const int warp_n = wid >> 1;  // 4 x 32 cols

    Ah += (long long)blockIdx.z * sA;  Al += (long long)blockIdx.z * sA;
    Bh += (long long)blockIdx.z * sB;  Bl += (long long)blockIdx.z * sB;
    if (Cf)  Cf  += (long long)blockIdx.z * sC;
    if (Chi) { Chi += (long long)blockIdx.z * sC; Clo += (long long)blockIdx.z * sC; }

    const long long m0 = (long long)blockIdx.y * TM;
    const long long n0 = (long long)blockIdx.x * TN;

    // ldmatrix per-lane offsets (bytes) within a tile:
    // A (.x4 for one 16x16 block): lanes 0-7 rows 0-7 @k0, 8-15 rows 8-15 @k0,
    //                              16-23 rows 0-7 @k8, 24-31 rows 8-15 @k8
    const uint32_t a_off = (uint32_t)(warp_m * 64 * ROWB)
        + ((lane & 7) + ((lane >> 3) & 1) * 8) * ROWB + (lane >> 4) * 16;
    // B (.x4 packing two n-blocks): lanes 0-7 rows n0-7 @k0, 8-15 rows n0-7 @k8,
    //                               16-23 rows n8-15 @k0, 24-31 rows n8-15 @k8
    const uint32_t b_off = (uint32_t)(warp_n * 32 * ROWB)
        + ((lane & 7) + (lane >> 4) * 8) * ROWB + ((lane >> 3) & 1) * 16;

    const uint32_t smem_s0 = (uint32_t)__cvta_generic_to_shared(smem);

    float acc[4][4][4];
    #pragma unroll
    for (int i = 0; i < 4; i++)
        #pragma unroll
        for (int j = 0; j < 4; j++)
            #pragma unroll
            for (int q = 0; q < 4; q++) acc[i][j][q] = 0.f;

    const int nkt = K / TKB;

    stage_loads(smem, tid, Ah, Al, ldA, m0, Bh, Bl, ldB, n0, 0);
    CP_COMMIT();

    for (int kt = 0; kt < nkt; ++kt) {
        const uint32_t cur = smem_s0 + (kt & 1) * STAGE_BYTES;
        if (kt + 1 < nkt) {
            stage_loads(smem + ((kt + 1) & 1) * STAGE_BYTES, tid, Ah, Al, ldA, m0,
                        Bh, Bl, ldB, n0, (long long)(kt + 1) * TKB);
            CP_COMMIT();
            CP_WAIT(1);
        } else {
            CP_WAIT(0);
        }
        __syncthreads();

        // 3 split terms, one fragment set live at a time
        compute_term(cur + SA_LO, cur + SB_HI, a_off, b_off, acc); // lo*hi
        compute_term(cur + SA_HI, cur + SB_LO, a_off, b_off, acc); // hi*lo
        compute_term(cur + SA_HI, cur + SB_HI, a_off, b_off, acc); // hi*hi

        __syncthreads();
    }

    // Epilogue
    const int r = lane >> 2;
    const int c = lane & 3;
    float bias_r0[4], bias_r1[4];
    if (bias_mode == 2) {
        #pragma unroll
        for (int mt = 0; mt < 4; mt++) {
            long long row = m0 + warp_m * 64 + mt * 16 + r;
            bias_r0[mt] = bias[row];
            bias_r1[mt] = bias[row + 8];
        }
    }

    #pragma unroll
    for (int mt = 0; mt < 4; mt++) {
        long long row = m0 + warp_m * 64 + mt * 16 + r;
        #pragma unroll
        for (int nt = 0; nt < 4; nt++) {
            long long col = n0 + warp_n * 32 + nt * 8 + 2 * c;
            float b0 = 0.f, b1 = 0.f, b0b = 0.f, b1b = 0.f;
            if (bias_mode == 1) {
                b0 = bias[col]; b1 = bias[col + 1]; b0b = b0; b1b = b1;
            } else if (bias_mode == 2) {
                b0 = bias_r0[mt]; b1 = b0; b0b = bias_r1[mt]; b1b = b0b;
            }
            float v00 = alpha * acc[mt][nt][0] + b0;
            float v01 = alpha * acc[mt][nt][1] + b1;
            float v10 = alpha * acc[mt][nt][2] + b0b;
            float v11 = alpha * acc[mt][nt][3] + b1b;
            if (Cf) {
                *reinterpret_cast<float2*>(Cf + row * ldC + col)       = make_float2(v00, v01);
                *reinterpret_cast<float2*>(Cf + (row + 8) * ldC + col) = make_float2(v10, v11);
            } else {
                __nv_bfloat16 h00 = __float2bfloat16(v00);
                __nv_bfloat16 h01 = __float2bfloat16(v01);
                __nv_bfloat16 h10 = __float2bfloat16(v10);
                __nv_bfloat16 h11 = __float2bfloat16(v11);
                __nv_bfloat162 hp0; hp0.x = h00; hp0.y = h01;
                __nv_bfloat162 hp1; hp1.x = h10; hp1.y = h11;
                __nv_bfloat162 lp0;
                lp0.x = __float2bfloat16(v00 - __bfloat162float(h00));
                lp0.y = __float2bfloat16(v01 - __bfloat162float(h01));
                __nv_bfloat162 lp1;
                lp1.x = __float2bfloat16(v10 - __bfloat162float(h10));
                lp1.y = __float2bfloat16(v11 - __bfloat162float(h11));
                *reinterpret_cast<__nv_bfloat162*>(Chi + row * ldC + col)       = hp0;
                *reinterpret_cast<__nv_bfloat162*>(Chi + (row + 8) * ldC + col) = hp1;
                *reinterpret_cast<__nv_bfloat162*>(Clo + row * ldC + col)       = lp0;
                *reinterpret_cast<__nv_bfloat162*>(Clo + (row + 8) * ldC + col) = lp1;
            }
        }
    }
}

// ---------------------------------------------------------------------------
// fp32 -> bf16 hi/lo split, vectorized (n must be a multiple of 4; true here)
// ---------------------------------------------------------------------------
__global__ void split_fp32(const float4* __restrict__ src,
                           __nv_bfloat162* __restrict__ hi,
                           __nv_bfloat162* __restrict__ lo, long long n4)
{
    long long i = (long long)blockIdx.x * blockDim.x + threadIdx.x;
    long long stride = (long long)gridDim.x * blockDim.x;
    for (; i < n4; i += stride) {
        float4 v = src[i];
        __nv_bfloat16 h0 = __float2bfloat16(v.x);
        __nv_bfloat16 h1 = __float2bfloat16(v.y);
        __nv_bfloat16 h2 = __float2bfloat16(v.z);
        __nv_bfloat16 h3 = __float2bfloat16(v.w);
        __nv_bfloat162 hp0; hp0.x = h0; hp0.y = h1;
        __nv_bfloat162 hp1; hp1.x = h2; hp1.y = h3;
        __nv_bfloat162 lp0;
        lp0.x = __float2bfloat16(v.x - __bfloat162float(h0));
        lp0.y = __float2bfloat16(v.y - __bfloat162float(h1));
        __nv_bfloat162 lp1;
        lp1.x = __float2bfloat16(v.z - __bfloat162float(h2));
        lp1.y = __float2bfloat16(v.w - __bfloat162float(h3));
        hi[2 * i] = hp0; hi[2 * i + 1] = hp1;
        lo[2 * i] = lp0; lo[2 * i + 1] = lp1;
    }
}

// ---------------------------------------------------------------------------
// Row softmax over 4096 cols; writes bf16 hi/lo split of probabilities.
// ---------------------------------------------------------------------------
__device__ __forceinline__ float warp_max(float v) {
    #pragma unroll
    for (int o = 16; o > 0; o >>= 1) v = fmaxf(v, __shfl_xor_sync(0xffffffffu, v, o));
    return v;
}
__device__ __forceinline__ float warp_sum(float v) {
    #pragma unroll
    for (int o = 16; o > 0; o >>= 1) v += __shfl_xor_sync(0xffffffffu, v, o);
    return v;
}

__global__ __launch_bounds__(256)
void softmax_rows(const float* __restrict__ S,
                  __nv_bfloat16* __restrict__ Phi, __nv_bfloat16* __restrict__ Plo)
{
    const int tid = threadIdx.x;
    const size_t base = (size_t)blockIdx.x * SDIM;
    const float* r = S + base;

    __shared__ float red[8];

    float v[16];
    float mx = -1e30f;
    #pragma unroll
    for (int i = 0; i < 16; i++) {
        v[i] = r[tid + i * 256];
        mx = fmaxf(mx, v[i]);
    }
    mx = warp_max(mx);
    if ((tid & 31) == 0) red[tid >> 5] = mx;
    __syncthreads();
    {
        float t = (tid < 8) ? red[tid] : -1e30f;
        t = warp_max(t);
        if (tid == 0) red[0] = t;
    }
    __syncthreads();
    mx = red[0];
    __syncthreads();

    float sum = 0.f;
    #pragma unroll
    for (int i = 0; i < 16; i++) {
        v[i] = __expf(v[i] - mx);
        sum += v[i];
    }
    sum = warp_sum(sum);
    if ((tid & 31) == 0) red[tid >> 5] = sum;
    __syncthreads();
    {
        float t = (tid < 8) ? red[tid] : 0.f;
        t = warp_sum(t);
        if (tid == 0) red[0] = t;
    }
    __syncthreads();
    const float inv = 1.f / red[0];

    #pragma unroll
    for (int i = 0; i < 16; i++) {
        float p = v[i] * inv;
        __nv_bfloat16 h = __float2bfloat16(p);
        __nv_bfloat16 l = __float2bfloat16(p - __bfloat162float(h));
        Phi[base + tid + i * 256] = h;
        Plo[base + tid + i * 256] = l;
    }
}

// ---------------------------------------------------------------------------
// Launch
// ---------------------------------------------------------------------------
extern "C" void kernel_launch(void* const* d_in, const int* in_sizes, int n_in,
                              void* d_out, int out_size)
{
    const float* x  = (const float*)d_in[0];
    const float* Wq = (const float*)d_in[1];
    const float* bq = (const float*)d_in[2];
    const float* Wk = (const float*)d_in[3];
    const float* bk = (const float*)d_in[4];
    const float* Wv = (const float*)d_in[5];
    const float* bv = (const float*)d_in[6];
    const float* Wo = (const float*)d_in[7];
    const float* bo = (const float*)d_in[8];
    float* out = (float*)d_out;

    cudaFuncSetAttribute(gemm_nt_bf3, cudaFuncAttributeMaxDynamicSharedMemorySize, DSMEM_BYTES);

    const dim3 blk(256);

    // 1) split inputs to bf16 hi/lo
    split_fp32<<<2048, 256>>>((const float4*)x,  (__nv_bfloat162*)g_xhi,  (__nv_bfloat162*)g_xlo,  (long long)MDIM * HDIM / 4);
    split_fp32<<<512,  256>>>((const float4*)Wq, (__nv_bfloat162*)g_wqhi, (__nv_bfloat162*)g_wqlo, (long long)HDIM * HDIM / 4);
    split_fp32<<<512,  256>>>((const float4*)Wk, (__nv_bfloat162*)g_wkhi, (__nv_bfloat162*)g_wklo, (long long)HDIM * HDIM / 4);
    split_fp32<<<512,  256>>>((const float4*)Wv, (__nv_bfloat162*)g_wvhi, (__nv_bfloat162*)g_wvlo, (long long)HDIM * HDIM / 4);
    split_fp32<<<512,  256>>>((const float4*)Wo, (__nv_bfloat162*)g_wohi, (__nv_bfloat162*)g_wolo, (long long)HDIM * HDIM / 4);

    // 2) Q = x Wq^T + bq  -> split bf16   [8192 x 1024]
    dim3 gproj(HDIM / TN, MDIM / TM, 1);   // (8, 64)
    gemm_nt_bf3<<<gproj, blk, DSMEM_BYTES>>>(g_xhi, g_xlo, HDIM, g_wqhi, g_wqlo, HDIM,
        nullptr, g_qhi, g_qlo, HDIM, bq, 1, 1.f, HDIM, 0, 0, 0);
    // 3) K
    gemm_nt_bf3<<<gproj, blk, DSMEM_BYTES>>>(g_xhi, g_xlo, HDIM, g_wkhi, g_wklo, HDIM,
        nullptr, g_khi, g_klo, HDIM, bk, 1, 1.f, HDIM, 0, 0, 0);
    // 4) V^T = Wv x^T + bv(row)  -> split bf16   [1024 x 8192]
    dim3 gvt(MDIM / TN, HDIM / TM, 1);     // (64, 8)
    gemm_nt_bf3<<<gvt, blk, DSMEM_BYTES>>>(g_wvhi, g_wvlo, HDIM, g_xhi, g_xlo, HDIM,
        nullptr, g_vthi, g_vtlo, MDIM, bv, 2, 1.f, HDIM, 0, 0, 0);

    // 5) scores = Q K^T / 8 (per batch) -> fp32
    dim3 gsc(SDIM / TN, SDIM / TM, BDIM);  // (32, 32, 2)
    gemm_nt_bf3<<<gsc, blk, DSMEM_BYTES>>>(g_qhi, g_qlo, HDIM, g_khi, g_klo, HDIM,
        g_s, nullptr, nullptr, SDIM, nullptr, 0, 0.125f, HDIM,
        (long long)SDIM * HDIM, (long long)SDIM * HDIM, (long long)SDIM * SDIM);

    // 6) softmax -> split bf16 P
    softmax_rows<<<BDIM * SDIM, blk>>>(g_s, g_phi, g_plo);

    // 7) attn = P V (per batch): A=P [4096x4096], B=V^T [1024 x 8192] -> split bf16
    dim3 gpv(HDIM / TN, SDIM / TM, BDIM);  // (8, 32, 2)
    gemm_nt_bf3<<<gpv, blk, DSMEM_BYTES>>>(g_phi, g_plo, SDIM, g_vthi, g_vtlo, MDIM,
        nullptr, g_athi, g_atlo, HDIM, nullptr, 0, 1.f, SDIM,
        (long long)SDIM * SDIM, (long long)SDIM, (long long)SDIM * HDIM);

    // 8) out = attn Wo^T + bo -> fp32
    gemm_nt_bf3<<<gproj, blk, DSMEM_BYTES>>>(g_athi, g_atlo, HDIM, g_wohi, g_wolo, HDIM,
        out, nullptr, nullptr, HDIM, bo, 1, 1.f, HDIM, 0, 0, 0);
}

// round 7
// speedup vs baseline: 2.0084x; 2.0084x over previous
#include <cuda_runtime.h>
#include <math.h>

// Problem shape: B=2, S=4096, H=1024, M=B*S=8192
#define BDIM 2
#define SDIM 4096
#define HDIM 1024
#define MDIM 8192

#define BM 128
#define BN 128
#define BK 16
#define PAD 132   // floats per smem k-row (128 payload + 4 pad)

// Scratch
__device__ float g_q[(size_t)MDIM * HDIM];
__device__ float g_k[(size_t)MDIM * HDIM];
__device__ float g_v[(size_t)MDIM * HDIM];
__device__ float g_attn[(size_t)MDIM * HDIM];
__device__ float g_s[(size_t)BDIM * SDIM * SDIM];

// ---------------------------------------------------------------------------
// NT GEMM: C[m,n] = alpha * sum_k A[m,k]*B[n,k] + bias[n]
// A:[M,K], B:[N,K], both row-major (K contiguous). M,N % 128 == 0, K % 16 == 0.
// smem holds transposed tiles As[k][m], Bs[k][n]; register-prefetch double buffer.
// ---------------------------------------------------------------------------
__global__ __launch_bounds__(256, 2)
void sgemm_nt(const float* __restrict__ A, const float* __restrict__ B,
              const float* __restrict__ bias, float* __restrict__ C,
              int M, int N, int K, float alpha,
              long long sA, long long sB, long long sC)
{
    A += (long long)blockIdx.z * sA;
    B += (long long)blockIdx.z * sB;
    C += (long long)blockIdx.z * sC;

    __shared__ float As[2][BK * PAD];
    __shared__ float Bs[2][BK * PAD];

    const int tid = threadIdx.x;
    const int tx = tid & 15;    // 0..15 column groups
    const int ty = tid >> 4;    // 0..15 row groups

    const int m0 = blockIdx.y * BM;
    const int n0 = blockIdx.x * BN;

    // Global->smem mapping: each thread owns one row (lrow) and 8 k-values
    // (two float4 at lk and lk+8).
    const int lrow = tid >> 1;          // 0..127
    const int lk   = (tid & 1) * 4;     // 0 or 4

    const float* Ap = A + (long long)(m0 + lrow) * K + lk;
    const float* Bp = B + (long long)(n0 + lrow) * K + lk;

    const int nt = K / BK;

    float4 pa0, pa1, pb0, pb1;
    pa0 = *reinterpret_cast<const float4*>(Ap);
    pa1 = *reinterpret_cast<const float4*>(Ap + 8);
    pb0 = *reinterpret_cast<const float4*>(Bp);
    pb1 = *reinterpret_cast<const float4*>(Bp + 8);

    // transposed stores: As[k][m]
    #pragma unroll
    for (int i = 0; i < 4; i++) {
        As[0][(lk + i) * PAD + lrow]     = (&pa0.x)[i];
        As[0][(lk + 8 + i) * PAD + lrow] = (&pa1.x)[i];
        Bs[0][(lk + i) * PAD + lrow]     = (&pb0.x)[i];
        Bs[0][(lk + 8 + i) * PAD + lrow] = (&pb1.x)[i];
    }
    __syncthreads();

    float acc[8][8];
    #pragma unroll
    for (int i = 0; i < 8; i++)
        #pragma unroll
        for (int j = 0; j < 8; j++) acc[i][j] = 0.f;

    for (int t = 0; t < nt; ++t) {
        const int cur = t & 1;
        if (t + 1 < nt) {
            const long long off = (long long)(t + 1) * BK;
            pa0 = *reinterpret_cast<const float4*>(Ap + off);
            pa1 = *reinterpret_cast<const float4*>(Ap + off + 8);
            pb0 = *reinterpret_cast<const float4*>(Bp + off);
            pb1 = *reinterpret_cast<const float4*>(Bp + off + 8);
        }

        #pragma unroll
        for (int kk = 0; kk < BK; ++kk) {
            const float* ar = &As[cur][kk * PAD];
            const float* br = &Bs[cur][kk * PAD];
            float4 a0 = *reinterpret_cast<const float4*>(ar + ty * 4);
            float4 a1 = *reinterpret_cast<const float4*>(ar + 64 + ty * 4);
            float4 b0 = *reinterpret_cast<const float4*>(br + tx * 4);
            float4 b1 = *reinterpret_cast<const float4*>(br + 64 + tx * 4);
            float ra[8] = {a0.x, a0.y, a0.z, a0.w, a1.x, a1.y, a1.z, a1.w};
            float rb[8] = {b0.x, b0.y, b0.z, b0.w, b1.x, b1.y, b1.z, b1.w};
            #pragma unroll
            for (int i = 0; i < 8; i++)
                #pragma unroll
                for (int j = 0; j < 8; j++)
                    acc[i][j] += ra[i] * rb[j];
        }

        if (t + 1 < nt) {
            const int nxt = cur ^ 1;
            #pragma unroll
            for (int i = 0; i < 4; i++) {
                As[nxt][(lk + i) * PAD + lrow]     = (&pa0.x)[i];
                As[nxt][(lk + 8 + i) * PAD + lrow] = (&pa1.x)[i];
                Bs[nxt][(lk + i) * PAD + lrow]     = (&pb0.x)[i];
                Bs[nxt][(lk + 8 + i) * PAD + lrow] = (&pb1.x)[i];
            }
        }
        __syncthreads();
    }

    // Epilogue
    float bb[8];
    #pragma unroll
    for (int jh = 0; jh < 2; jh++) {
        int n = n0 + jh * 64 + tx * 4;
        if (bias) {
            float4 b = *reinterpret_cast<const float4*>(bias + n);
            bb[jh*4+0] = b.x; bb[jh*4+1] = b.y; bb[jh*4+2] = b.z; bb[jh*4+3] = b.w;
        } else {
            bb[jh*4+0] = bb[jh*4+1] = bb[jh*4+2] = bb[jh*4+3] = 0.f;
        }
    }

    #pragma unroll
    for (int ih = 0; ih < 2; ih++) {
        #pragma unroll
        for (int ii = 0; ii < 4; ii++) {
            int m = m0 + ih * 64 + ty * 4 + ii;
            float* Crow = C + (long long)m * N;
            #pragma unroll
            for (int jh = 0; jh < 2; jh++) {
                int n = n0 + jh * 64 + tx * 4;
                float4 o;
                o.x = alpha * acc[ih*4+ii][jh*4+0] + bb[jh*4+0];
                o.y = alpha * acc[ih*4+ii][jh*4+1] + bb[jh*4+1];
                o.z = alpha * acc[ih*4+ii][jh*4+2] + bb[jh*4+2];
                o.w = alpha * acc[ih*4+ii][jh*4+3] + bb[jh*4+3];
                *reinterpret_cast<float4*>(Crow + n) = o;
            }
        }
    }
}

// ---------------------------------------------------------------------------
// NN GEMM: C[m,n] = sum_k A[m,k]*B[k,n]   (A:[M,K], B:[K,N], row-major)
// ---------------------------------------------------------------------------
__global__ __launch_bounds__(256, 2)
void sgemm_nn(const float* __restrict__ A, const float* __restrict__ B,
              float* __restrict__ C,
              int M, int N, int K,
              long long sA, long long sB, long long sC)
{
    A += (long long)blockIdx.z * sA;
    B += (long long)blockIdx.z * sB;
    C += (long long)blockIdx.z * sC;

    __shared__ float As[2][BK * PAD];
    __shared__ float Bs[2][BK * PAD];

    const int tid = threadIdx.x;
    const int tx = tid & 15;
    const int ty = tid >> 4;

    const int m0 = blockIdx.y * BM;
    const int n0 = blockIdx.x * BN;

    // A: transpose path (same as NT)
    const int lrow = tid >> 1;
    const int lk   = (tid & 1) * 4;
    // B: direct coalesced copy of [16][128] rows
    const int brow = tid >> 4;          // 0..15
    const int bcol = (tid & 15) * 4;    // 0..60

    const float* Ap = A + (long long)(m0 + lrow) * K + lk;
    const float* Bp = B + (long long)brow * N + n0 + bcol;

    const int nt = K / BK;

    float4 pa0, pa1, pb0, pb1;
    pa0 = *reinterpret_cast<const float4*>(Ap);
    pa1 = *reinterpret_cast<const float4*>(Ap + 8);
    pb0 = *reinterpret_cast<const float4*>(Bp);
    pb1 = *reinterpret_cast<const float4*>(Bp + 64);

    #pragma unroll
    for (int i = 0; i < 4; i++) {
        As[0][(lk + i) * PAD + lrow]     = (&pa0.x)[i];
        As[0][(lk + 8 + i) * PAD + lrow] = (&pa1.x)[i];
    }
    *reinterpret_cast<float4*>(&Bs[0][brow * PAD + bcol])      = pb0;
    *reinterpret_cast<float4*>(&Bs[0][brow * PAD + bcol + 64]) = pb1;
    __syncthreads();

    float acc[8][8];
    #pragma unroll
    for (int i = 0; i < 8; i++)
        #pragma unroll
        for (int j = 0; j < 8; j++) acc[i][j] = 0.f;

    for (int t = 0; t < nt; ++t) {
        const int cur = t & 1;
        if (t + 1 < nt) {
            const long long offA = (long long)(t + 1) * BK;
            const long long offB = (long long)(t + 1) * BK * N;
            pa0 = *reinterpret_cast<const float4*>(Ap + offA);
            pa1 = *reinterpret_cast<const float4*>(Ap + offA + 8);
            pb0 = *reinterpret_cast<const float4*>(Bp + offB);
            pb1 = *reinterpret_cast<const float4*>(Bp + offB + 64);
        }

        #pragma unroll
        for (int kk = 0; kk < BK; ++kk) {
            const float* ar = &As[cur][kk * PAD];
            const float* br = &Bs[cur][kk * PAD];
            float4 a0 = *reinterpret_cast<const float4*>(ar + ty * 4);
            float4 a1 = *reinterpret_cast<const float4*>(ar + 64 + ty * 4);
            float4 b0 = *reinterpret_cast<const float4*>(br + tx * 4);
            float4 b1 = *reinterpret_cast<const float4*>(br + 64 + tx * 4);
            float ra[8] = {a0.x, a0.y, a0.z, a0.w, a1.x, a1.y, a1.z, a1.w};
            float rb[8] = {b0.x, b0.y, b0.z, b0.w, b1.x, b1.y, b1.z, b1.w};
            #pragma unroll
            for (int i = 0; i < 8; i++)
                #pragma unroll
                for (int j = 0; j < 8; j++)
                    acc[i][j] += ra[i] * rb[j];
        }

        if (t + 1 < nt) {
            const int nxt = cur ^ 1;
            #pragma unroll
            for (int i = 0; i < 4; i++) {
                As[nxt][(lk + i) * PAD + lrow]     = (&pa0.x)[i];
                As[nxt][(lk + 8 + i) * PAD + lrow] = (&pa1.x)[i];
            }
            *reinterpret_cast<float4*>(&Bs[nxt][brow * PAD + bcol])      = pb0;
            *reinterpret_cast<float4*>(&Bs[nxt][brow * PAD + bcol + 64]) = pb1;
        }
        __syncthreads();
    }

    #pragma unroll
    for (int ih = 0; ih < 2; ih++) {
        #pragma unroll
        for (int ii = 0; ii < 4; ii++) {
            int m = m0 + ih * 64 + ty * 4 + ii;
            float* Crow = C + (long long)m * N;
            #pragma unroll
            for (int jh = 0; jh < 2; jh++) {
                int n = n0 + jh * 64 + tx * 4;
                float4 o;
                o.x = acc[ih*4+ii][jh*4+0];
                o.y = acc[ih*4+ii][jh*4+1];
                o.z = acc[ih*4+ii][jh*4+2];
                o.w = acc[ih*4+ii][jh*4+3];
                *reinterpret_cast<float4*>(Crow + n) = o;
            }
        }
    }
}

// ---------------------------------------------------------------------------
// Row softmax over 4096 columns, one block (256 threads) per row, in place.
// ---------------------------------------------------------------------------
__device__ __forceinline__ float warp_max(float v) {
    #pragma unroll
    for (int o = 16; o > 0; o >>= 1) v = fmaxf(v, __shfl_xor_sync(0xffffffffu, v, o));
    return v;
}
__device__ __forceinline__ float warp_sum(float v) {
    #pragma unroll
    for (int o = 16; o > 0; o >>= 1) v += __shfl_xor_sync(0xffffffffu, v, o);
    return v;
}

__global__ __launch_bounds__(256)
void softmax_rows(float* __restrict__ S)
{
    const int tid = threadIdx.x;
    float* r = S + (size_t)blockIdx.x * SDIM;

    __shared__ float red[8];

    float v[16];
    float mx = -1e30f;
    #pragma unroll
    for (int i = 0; i < 16; i++) {
        v[i] = r[tid + i * 256];
        mx = fmaxf(mx, v[i]);
    }
    mx = warp_max(mx);
    if ((tid & 31) == 0) red[tid >> 5] = mx;
    __syncthreads();
    {
        float t = (tid < 8) ? red[tid] : -1e30f;
        t = warp_max(t);
        if (tid == 0) red[0] = t;
    }
    __syncthreads();
    mx = red[0];
    __syncthreads();

    float sum = 0.f;
    #pragma unroll
    for (int i = 0; i < 16; i++) {
        v[i] = __expf(v[i] - mx);
        sum += v[i];
    }
    sum = warp_sum(sum);
    if ((tid & 31) == 0) red[tid >> 5] = sum;
    __syncthreads();
    {
        float t = (tid < 8) ? red[tid] : 0.f;
        t = warp_sum(t);
        if (tid == 0) red[0] = t;
    }
    __syncthreads();
    const float inv = 1.f / red[0];

    #pragma unroll
    for (int i = 0; i < 16; i++)
        r[tid + i * 256] = v[i] * inv;
}

// ---------------------------------------------------------------------------
// Launch
// ---------------------------------------------------------------------------
extern "C" void kernel_launch(void* const* d_in, const int* in_sizes, int n_in,
                              void* d_out, int out_size)
{
    const float* x  = (const float*)d_in[0];
    const float* Wq = (const float*)d_in[1];
    const float* bq = (const float*)d_in[2];
    const float* Wk = (const float*)d_in[3];
    const float* bk = (const float*)d_in[4];
    const float* Wv = (const float*)d_in[5];
    const float* bv = (const float*)d_in[6];
    const float* Wo = (const float*)d_in[7];
    const float* bo = (const float*)d_in[8];
    float* out = (float*)d_out;

    const dim3 blk(256);

    // QKV projections: [8192,1024] = x[8192,1024] @ W^T + b
    dim3 gproj(HDIM / BN, MDIM / BM, 1);   // (8, 64)
    sgemm_nt<<<gproj, blk>>>(x, Wq, bq, g_q, MDIM, HDIM, HDIM, 1.f, 0, 0, 0);
    sgemm_nt<<<gproj, blk>>>(x, Wk, bk, g_k, MDIM, HDIM, HDIM, 1.f, 0, 0, 0);
    sgemm_nt<<<gproj, blk>>>(x, Wv, bv, g_v, MDIM, HDIM, HDIM, 1.f, 0, 0, 0);

    // scores = Q K^T / 8  (per batch)
    dim3 gsc(SDIM / BN, SDIM / BM, BDIM);  // (32, 32, 2)
    sgemm_nt<<<gsc, blk>>>(g_q, g_k, nullptr, g_s, SDIM, SDIM, HDIM, 0.125f,
                           (long long)SDIM * HDIM, (long long)SDIM * HDIM,
                           (long long)SDIM * SDIM);

    // softmax over rows (8192 rows of 4096), in place
    softmax_rows<<<BDIM * SDIM, blk>>>(g_s);

    // attn = P V  (per batch)
    dim3 gpv(HDIM / BN, SDIM / BM, BDIM);  // (8, 32, 2)
    sgemm_nn<<<gpv, blk>>>(g_s, g_v, g_attn, SDIM, HDIM, SDIM,
                           (long long)SDIM * SDIM, (long long)SDIM * HDIM,
                           (long long)SDIM * HDIM);

    // out = attn Wo^T + bo
    sgemm_nt<<<gproj, blk>>>(g_attn, Wo, bo, out, MDIM, HDIM, HDIM, 1.f, 0, 0, 0);
}

// round 8
// speedup vs baseline: 2.1217x; 1.0564x over previous
#include <cuda_runtime.h>
#include <math.h>

// Problem shape: B=2, S=4096, H=1024, M=B*S=8192
#define BDIM 2
#define SDIM 4096
#define HDIM 1024
#define MDIM 8192

#define BM 128
#define BN 128
#define BK 16
#define APAD 132                 // floats per As k-row
#define BPAD 264                 // floats per Bs2 k-row (duplicated pairs)
#define AS_F (BK * APAD)         // 2112 floats
#define BS_F (BK * BPAD)         // 4224 floats
#define STG_F (AS_F + BS_F)      // 6336 floats per stage
#define DSMEM_BYTES (2 * STG_F * 4)  // 50688 bytes

// Scratch
__device__ float g_q[(size_t)MDIM * HDIM];
__device__ float g_k[(size_t)MDIM * HDIM];
__device__ float g_v[(size_t)MDIM * HDIM];
__device__ float g_attn[(size_t)MDIM * HDIM];
__device__ float g_s[(size_t)BDIM * SDIM * SDIM];

typedef unsigned long long u64;

__device__ __forceinline__ void ffma2(u64& d, u64 a, u64 b) {
    asm("fma.rn.f32x2 %0, %1, %2, %0;" : "+l"(d) : "l"(a), "l"(b));
}
__device__ __forceinline__ float2 unpack2(u64 v) {
    float2 f;
    asm("mov.b64 {%0, %1}, %2;" : "=f"(f.x), "=f"(f.y) : "l"(v));
    return f;
}

// ---------------------------------------------------------------------------
// Shared inner machinery: given As[k][m] (transposed) and Bs2[k][2n] (dup
// pairs), each thread computes an 8(m) x 8(n) tile as 4x8 f32x2 (m-pairs).
// ---------------------------------------------------------------------------
__device__ __forceinline__ void compute_stage(
    const float* __restrict__ asb, const float* __restrict__ bsb,
    int ty, int tx, u64 acc[4][8])
{
    #pragma unroll
    for (int kk = 0; kk < BK; ++kk) {
        const float* ar = asb + kk * APAD;
        const float* br = bsb + kk * BPAD;
        ulonglong2 av0 = *reinterpret_cast<const ulonglong2*>(ar + ty * 4);
        ulonglong2 av1 = *reinterpret_cast<const ulonglong2*>(ar + 64 + ty * 4);
        ulonglong2 bv0 = *reinterpret_cast<const ulonglong2*>(br + 8 * tx);
        ulonglong2 bv1 = *reinterpret_cast<const ulonglong2*>(br + 8 * tx + 4);
        ulonglong2 bv2 = *reinterpret_cast<const ulonglong2*>(br + 128 + 8 * tx);
        ulonglong2 bv3 = *reinterpret_cast<const ulonglong2*>(br + 128 + 8 * tx + 4);
        u64 a_[4] = {av0.x, av0.y, av1.x, av1.y};
        u64 b_[8] = {bv0.x, bv0.y, bv1.x, bv1.y, bv2.x, bv2.y, bv3.x, bv3.y};
        #pragma unroll
        for (int mi = 0; mi < 4; mi++)
            #pragma unroll
            for (int j = 0; j < 8; j++)
                ffma2(acc[mi][j], a_[mi], b_[j]);
    }
}

__device__ __forceinline__ void epilogue_store(
    u64 acc[4][8], float* __restrict__ C, long long ldC,
    long long m0, long long n0, int ty, int tx,
    const float* __restrict__ bias, float alpha)
{
    float bb[8];
    #pragma unroll
    for (int jh = 0; jh < 2; jh++) {
        long long n = n0 + jh * 64 + tx * 4;
        if (bias) {
            float4 b = *reinterpret_cast<const float4*>(bias + n);
            bb[jh*4+0] = b.x; bb[jh*4+1] = b.y; bb[jh*4+2] = b.z; bb[jh*4+3] = b.w;
        } else {
            bb[jh*4+0] = bb[jh*4+1] = bb[jh*4+2] = bb[jh*4+3] = 0.f;
        }
    }
    #pragma unroll
    for (int mi = 0; mi < 4; mi++) {
        long long r0 = (mi < 2) ? (m0 + ty * 4 + 2 * mi)
                                : (m0 + 64 + ty * 4 + 2 * (mi - 2));
        float2 p[8];
        #pragma unroll
        for (int j = 0; j < 8; j++) p[j] = unpack2(acc[mi][j]);
        #pragma unroll
        for (int jh = 0; jh < 2; jh++) {
            long long n = n0 + jh * 64 + tx * 4;
            float4 lo, hi;
            lo.x = alpha * p[jh*4+0].x + bb[jh*4+0];
            lo.y = alpha * p[jh*4+1].x + bb[jh*4+1];
            lo.z = alpha * p[jh*4+2].x + bb[jh*4+2];
            lo.w = alpha * p[jh*4+3].x + bb[jh*4+3];
            hi.x = alpha * p[jh*4+0].y + bb[jh*4+0];
            hi.y = alpha * p[jh*4+1].y + bb[jh*4+1];
            hi.z = alpha * p[jh*4+2].y + bb[jh*4+2];
            hi.w = alpha * p[jh*4+3].y + bb[jh*4+3];
            *reinterpret_cast<float4*>(C + r0 * ldC + n)       = lo;
            *reinterpret_cast<float4*>(C + (r0 + 1) * ldC + n) = hi;
        }
    }
}

// ---------------------------------------------------------------------------
// NT GEMM: C[m,n] = alpha * sum_k A[m,k]*B[n,k] + bias[n]
// A:[M,K], B:[N,K] row-major. M,N % 128 == 0, K % 16 == 0.
// ---------------------------------------------------------------------------
__global__ __launch_bounds__(256, 2)
void sgemm_nt(const float* __restrict__ A, const float* __restrict__ B,
              const float* __restrict__ bias, float* __restrict__ C,
              int M, int N, int K, float alpha,
              long long sA, long long sB, long long sC)
{
    extern __shared__ float sm[];

    A += (long long)blockIdx.z * sA;
    B += (long long)blockIdx.z * sB;
    C += (long long)blockIdx.z * sC;

    const int tid = threadIdx.x;
    const int tx = tid & 15;
    const int ty = tid >> 4;

    const long long m0 = (long long)blockIdx.y * BM;
    const long long n0 = (long long)blockIdx.x * BN;

    const int lrow = tid >> 1;
    const int lk   = (tid & 1) * 4;

    const float* Ap = A + (m0 + lrow) * K + lk;
    const float* Bp = B + (n0 + lrow) * K + lk;

    const int nt = K / BK;

    float4 pa0, pa1, pb0, pb1;
    pa0 = *reinterpret_cast<const float4*>(Ap);
    pa1 = *reinterpret_cast<const float4*>(Ap + 8);
    pb0 = *reinterpret_cast<const float4*>(Bp);
    pb1 = *reinterpret_cast<const float4*>(Bp + 8);

    {
        float* as0 = sm;
        float* bs0 = sm + AS_F;
        #pragma unroll
        for (int i = 0; i < 4; i++) {
            as0[(lk + i) * APAD + lrow]     = (&pa0.x)[i];
            as0[(lk + 8 + i) * APAD + lrow] = (&pa1.x)[i];
            float v0 = (&pb0.x)[i], v1 = (&pb1.x)[i];
            *reinterpret_cast<float2*>(&bs0[(lk + i) * BPAD + 2 * lrow])     = make_float2(v0, v0);
            *reinterpret_cast<float2*>(&bs0[(lk + 8 + i) * BPAD + 2 * lrow]) = make_float2(v1, v1);
        }
    }
    __syncthreads();

    u64 acc[4][8];
    #pragma unroll
    for (int i = 0; i < 4; i++)
        #pragma unroll
        for (int j = 0; j < 8; j++) acc[i][j] = 0ULL;

    for (int t = 0; t < nt; ++t) {
        const int cur = t & 1;
        if (t + 1 < nt) {
            const long long off = (long long)(t + 1) * BK;
            pa0 = *reinterpret_cast<const float4*>(Ap + off);
            pa1 = *reinterpret_cast<const float4*>(Ap + off + 8);
            pb0 = *reinterpret_cast<const float4*>(Bp + off);
            pb1 = *reinterpret_cast<const float4*>(Bp + off + 8);
        }

        compute_stage(sm + cur * STG_F, sm + cur * STG_F + AS_F, ty, tx, acc);

        if (t + 1 < nt) {
            float* asn = sm + (cur ^ 1) * STG_F;
            float* bsn = asn + AS_F;
            #pragma unroll
            for (int i = 0; i < 4; i++) {
                asn[(lk + i) * APAD + lrow]     = (&pa0.x)[i];
                asn[(lk + 8 + i) * APAD + lrow] = (&pa1.x)[i];
                float v0 = (&pb0.x)[i], v1 = (&pb1.x)[i];
                *reinterpret_cast<float2*>(&bsn[(lk + i) * BPAD + 2 * lrow])     = make_float2(v0, v0);
                *reinterpret_cast<float2*>(&bsn[(lk + 8 + i) * BPAD + 2 * lrow]) = make_float2(v1, v1);
            }
        }
        __syncthreads();
    }

    epilogue_store(acc, C, N, m0, n0, ty, tx, bias, alpha);
}

// ---------------------------------------------------------------------------
// NN GEMM: C[m,n] = sum_k A[m,k]*B[k,n]   (A:[M,K], B:[K,N], row-major)
// ---------------------------------------------------------------------------
__global__ __launch_bounds__(256, 2)
void sgemm_nn(const float* __restrict__ A, const float* __restrict__ B,
              float* __restrict__ C,
              int M, int N, int K,
              long long sA, long long sB, long long sC)
{
    extern __shared__ float sm[];

    A += (long long)blockIdx.z * sA;
    B += (long long)blockIdx.z * sB;
    C += (long long)blockIdx.z * sC;

    const int tid = threadIdx.x;
    const int tx = tid & 15;
    const int ty = tid >> 4;

    const long long m0 = (long long)blockIdx.y * BM;
    const long long n0 = (long long)blockIdx.x * BN;

    const int lrow = tid >> 1;
    const int lk   = (tid & 1) * 4;
    const int brow = tid >> 4;           // 0..15
    const int bcol = (tid & 15) * 4;     // 0..60

    const float* Ap = A + (m0 + lrow) * K + lk;
    const float* Bp = B + (long long)brow * N + n0 + bcol;

    const int nt = K / BK;

    float4 pa0, pa1, pb0, pb1;
    pa0 = *reinterpret_cast<const float4*>(Ap);
    pa1 = *reinterpret_cast<const float4*>(Ap + 8);
    pb0 = *reinterpret_cast<const float4*>(Bp);
    pb1 = *reinterpret_cast<const float4*>(Bp + 64);

    {
        float* as0 = sm;
        float* bs0 = sm + AS_F;
        #pragma unroll
        for (int i = 0; i < 4; i++) {
            as0[(lk + i) * APAD + lrow]     = (&pa0.x)[i];
            as0[(lk + 8 + i) * APAD + lrow] = (&pa1.x)[i];
            float v0 = (&pb0.x)[i], v1 = (&pb1.x)[i];
            *reinterpret_cast<float2*>(&bs0[brow * BPAD + 2 * (bcol + i)])      = make_float2(v0, v0);
            *reinterpret_cast<float2*>(&bs0[brow * BPAD + 2 * (64 + bcol + i)]) = make_float2(v1, v1);
        }
    }
    __syncthreads();

    u64 acc[4][8];
    #pragma unroll
    for (int i = 0; i < 4; i++)
        #pragma unroll
        for (int j = 0; j < 8; j++) acc[i][j] = 0ULL;

    for (int t = 0; t < nt; ++t) {
        const int cur = t & 1;
        if (t + 1 < nt) {
            const long long offA = (long long)(t + 1) * BK;
            const long long offB = (long long)(t + 1) * BK * N;
            pa0 = *reinterpret_cast<const float4*>(Ap + offA);
            pa1 = *reinterpret_cast<const float4*>(Ap + offA + 8);
            pb0 = *reinterpret_cast<const float4*>(Bp + offB);
            pb1 = *reinterpret_cast<const float4*>(Bp + offB + 64);
        }

        compute_stage(sm + cur * STG_F, sm + cur * STG_F + AS_F, ty, tx, acc);

        if (t + 1 < nt) {
            float* asn = sm + (cur ^ 1) * STG_F;
            float* bsn = asn + AS_F;
            #pragma unroll
            for (int i = 0; i < 4; i++) {
                asn[(lk + i) * APAD + lrow]     = (&pa0.x)[i];
                asn[(lk + 8 + i) * APAD + lrow] = (&pa1.x)[i];
                float v0 = (&pb0.x)[i], v1 = (&pb1.x)[i];
                *reinterpret_cast<float2*>(&bsn[brow * BPAD + 2 * (bcol + i)])      = make_float2(v0, v0);
                *reinterpret_cast<float2*>(&bsn[brow * BPAD + 2 * (64 + bcol + i)]) = make_float2(v1, v1);
            }
        }
        __syncthreads();
    }

    epilogue_store(acc, C, N, m0, n0, ty, tx, nullptr, 1.f);
}

// ---------------------------------------------------------------------------
// Row softmax over 4096 columns, one block (256 threads) per row, in place.
// ---------------------------------------------------------------------------
__device__ __forceinline__ float warp_max(float v) {
    #pragma unroll
    for (int o = 16; o > 0; o >>= 1) v = fmaxf(v, __shfl_xor_sync(0xffffffffu, v, o));
    return v;
}
__device__ __forceinline__ float warp_sum(float v) {
    #pragma unroll
    for (int o = 16; o > 0; o >>= 1) v += __shfl_xor_sync(0xffffffffu, v, o);
    return v;
}

__global__ __launch_bounds__(256)
void softmax_rows(float* __restrict__ S)
{
    const int tid = threadIdx.x;
    float* r = S + (size_t)blockIdx.x * SDIM;

    __shared__ float red[8];

    float v[16];
    float mx = -1e30f;
    #pragma unroll
    for (int i = 0; i < 16; i++) {
        v[i] = r[tid + i * 256];
        mx = fmaxf(mx, v[i]);
    }
    mx = warp_max(mx);
    if ((tid & 31) == 0) red[tid >> 5] = mx;
    __syncthreads();
    {
        float t = (tid < 8) ? red[tid] : -1e30f;
        t = warp_max(t);
        if (tid == 0) red[0] = t;
    }
    __syncthreads();
    mx = red[0];
    __syncthreads();

    float sum = 0.f;
    #pragma unroll
    for (int i = 0; i < 16; i++) {
        v[i] = __expf(v[i] - mx);
        sum += v[i];
    }
    sum = warp_sum(sum);
    if ((tid & 31) == 0) red[tid >> 5] = sum;
    __syncthreads();
    {
        float t = (tid < 8) ? red[tid] : 0.f;
        t = warp_sum(t);
        if (tid == 0) red[0] = t;
    }
    __syncthreads();
    const float inv = 1.f / red[0];

    #pragma unroll
    for (int i = 0; i < 16; i++)
        r[tid + i * 256] = v[i] * inv;
}

// ---------------------------------------------------------------------------
// Launch
// ---------------------------------------------------------------------------
extern "C" void kernel_launch(void* const* d_in, const int* in_sizes, int n_in,
                              void* d_out, int out_size)
{
    const float* x  = (const float*)d_in[0];
    const float* Wq = (const float*)d_in[1];
    const float* bq = (const float*)d_in[2];
    const float* Wk = (const float*)d_in[3];
    const float* bk = (const float*)d_in[4];
    const float* Wv = (const float*)d_in[5];
    const float* bv = (const float*)d_in[6];
    const float* Wo = (const float*)d_in[7];
    const float* bo = (const float*)d_in[8];
    float* out = (float*)d_out;

    cudaFuncSetAttribute(sgemm_nt, cudaFuncAttributeMaxDynamicSharedMemorySize, DSMEM_BYTES);
    cudaFuncSetAttribute(sgemm_nn, cudaFuncAttributeMaxDynamicSharedMemorySize, DSMEM_BYTES);

    const dim3 blk(256);

    // QKV projections: [8192,1024] = x[8192,1024] @ W^T + b
    dim3 gproj(HDIM / BN, MDIM / BM, 1);   // (8, 64)
    sgemm_nt<<<gproj, blk, DSMEM_BYTES>>>(x, Wq, bq, g_q, MDIM, HDIM, HDIM, 1.f, 0, 0, 0);
    sgemm_nt<<<gproj, blk, DSMEM_BYTES>>>(x, Wk, bk, g_k, MDIM, HDIM, HDIM, 1.f, 0, 0, 0);
    sgemm_nt<<<gproj, blk, DSMEM_BYTES>>>(x, Wv, bv, g_v, MDIM, HDIM, HDIM, 1.f, 0, 0, 0);

    // scores = Q K^T / 8  (per batch)
    dim3 gsc(SDIM / BN, SDIM / BM, BDIM);  // (32, 32, 2)
    sgemm_nt<<<gsc, blk, DSMEM_BYTES>>>(g_q, g_k, nullptr, g_s, SDIM, SDIM, HDIM, 0.125f,
                                        (long long)SDIM * HDIM, (long long)SDIM * HDIM,
                                        (long long)SDIM * SDIM);

    // softmax over rows (8192 rows of 4096), in place
    softmax_rows<<<BDIM * SDIM, blk>>>(g_s);

    // attn = P V  (per batch)
    dim3 gpv(HDIM / BN, SDIM / BM, BDIM);  // (8, 32, 2)
    sgemm_nn<<<gpv, blk, DSMEM_BYTES>>>(g_s, g_v, g_attn, SDIM, HDIM, SDIM,
                                        (long long)SDIM * SDIM, (long long)SDIM * HDIM,
                                        (long long)SDIM * HDIM);

    // out = attn Wo^T + bo
    sgemm_nt<<<gproj, blk, DSMEM_BYTES>>>(g_attn, Wo, bo, out, MDIM, HDIM, HDIM, 1.f, 0, 0, 0);
}